// round 17
// baseline (speedup 1.0000x reference)
#include <cuda_runtime.h>
#include <cuda_bf16.h>
#include <cstdint>

// u_quant_weight_linear: out[o,i] = clip(rint(w[o,i]/s), -qmax, qmax) * s
//   s = max(alh[o], 1e-5); b = rint(clip(|bit[o]|,1,6)); qmax = max(2^(b-1)-1,1)
//
// R17: CTA-granularity probe on the converged R8 optimum (6 runs:
// 48.99-50.24us kernel, 6.06-6.22 TB/s). Single-variable change:
// 128-thread CTAs (launch_bounds(128,10), 11008 blocks) instead of
// 256-thread (x5504). Identical per-thread body: batch 4 front-batched
// LDG.E.256/STG.E.256, 128B in flight, 48-reg budget, 62.5% theoretical occ.
// Tests whether the persistent ~10-pt achieved-occ gap (52-53% measured)
// is CTA retirement-drain granularity: 4-warp refill units vs 8-warp.

#define VEC8_PER_ROW 1376u
#define NTHR         128
#define BATCH        4
#define CHUNK        (NTHR * BATCH)          // 512 vec8
#define NBLK         11008                    // 11008*512 = 5636096 exactly

struct f8 { float4 a, b; };

__device__ __forceinline__ f8 ldg256_cs(const float* p)
{
    f8 r;
    asm volatile("ld.global.cs.v8.f32 {%0,%1,%2,%3,%4,%5,%6,%7}, [%8];"
                 : "=f"(r.a.x), "=f"(r.a.y), "=f"(r.a.z), "=f"(r.a.w),
                   "=f"(r.b.x), "=f"(r.b.y), "=f"(r.b.z), "=f"(r.b.w)
                 : "l"(p));
    return r;
}

__device__ __forceinline__ void stg256_cs(float* p, f8 v)
{
    asm volatile("st.global.cs.v8.f32 [%0], {%1,%2,%3,%4,%5,%6,%7,%8};"
                 :: "l"(p),
                    "f"(v.a.x), "f"(v.a.y), "f"(v.a.z), "f"(v.a.w),
                    "f"(v.b.x), "f"(v.b.y), "f"(v.b.z), "f"(v.b.w)
                 : "memory");
}

__device__ __forceinline__ void row_params(unsigned idx8,
                                           const float* __restrict__ alh,
                                           const float* __restrict__ bit,
                                           float& s, float& qmax)
{
    const unsigned r = idx8 / VEC8_PER_ROW;   // warp-uniform; const-div
    s = fmaxf(alh[r], 1e-5f);
    const float b = rintf(fminf(fmaxf(fabsf(bit[r]), 1.0f), 6.0f));
    qmax = fmaxf(exp2f(b - 1.0f) - 1.0f, 1.0f);
}

__device__ __forceinline__ float qf(float x, float s, float qmin, float qmax)
{
    // True IEEE divide: rint decisions must match the reference exactly.
    return fminf(fmaxf(rintf(x / s), qmin), qmax) * s;
}

__device__ __forceinline__ f8 quant8(f8 v, float s, float qmax)
{
    const float qmin = -qmax;
    v.a.x = qf(v.a.x, s, qmin, qmax);  v.a.y = qf(v.a.y, s, qmin, qmax);
    v.a.z = qf(v.a.z, s, qmin, qmax);  v.a.w = qf(v.a.w, s, qmin, qmax);
    v.b.x = qf(v.b.x, s, qmin, qmax);  v.b.y = qf(v.b.y, s, qmin, qmax);
    v.b.z = qf(v.b.z, s, qmin, qmax);  v.b.w = qf(v.b.w, s, qmin, qmax);
    return v;
}

__global__ __launch_bounds__(NTHR, 10)
void fake_quant_kernel(const float* __restrict__ w,
                       const float* __restrict__ alh,
                       const float* __restrict__ bit,
                       float* __restrict__ out)
{
    const unsigned base = blockIdx.x * CHUNK + threadIdx.x;   // vec8 index

    // Front-batch all 4 256-bit loads: 128B genuinely in flight per thread.
    f8 v[BATCH];
    #pragma unroll
    for (int i = 0; i < BATCH; i++)
        v[i] = ldg256_cs(w + (size_t)(base + i * NTHR) * 8u);

    #pragma unroll
    for (int i = 0; i < BATCH; i++) {
        const unsigned idx8 = base + i * NTHR;
        float s, qmax;
        row_params(idx8, alh, bit, s, qmax);
        stg256_cs(out + (size_t)idx8 * 8u, quant8(v[i], s, qmax));
    }
}

extern "C" void kernel_launch(void* const* d_in, const int* in_sizes, int n_in,
                              void* d_out, int out_size)
{
    const float* w   = (const float*)d_in[0];  // weight [4096, 11008]
    const float* alh = (const float*)d_in[1];  // [4096, 1]
    const float* bit = (const float*)d_in[2];  // [4096, 1]
    float* out = (float*)d_out;

    fake_quant_kernel<<<NBLK, NTHR>>>(w, alh, bit, out);
}